// round 12
// baseline (speedup 1.0000x reference)
#include <cuda_runtime.h>
#include <cstdint>
#include <math.h>
#include <float.h>

#define B_ROWS 128
#define V_COLS 128000
#define NV4 (V_COLS / 4)
#define TPB 1024
#define NBINS 16
#define CAPP 2048
#define CAPS 2048

// ---- smem layout (bytes) ----
#define OFF_MASS 0                    // double[16][1024] = 131072
#define OFF_CNT  131072               // uint [16][1024] =  65536
#define OFF_REDD 196608               // double[16][64]  =   8192
#define OFF_REDI 204800               // int   [16][64]  =   4096
#define OFF_BINM 208896               // double[16]      =    128
#define OFF_BINC 209024               // int   [16]      =     64
#define OFF_MISC 209088
#define SMEM_TOTAL 209600
// overlays valid after the level passes (mass/cnt regions dead):
#define OFF_BUFP  0                   // float [CAPP]  8192
#define OFF_BUFPE 8192                // double[CAPP] 16384
#define OFF_BUFS  24576               // u64   [CAPS] 16384
#define OFF_CUMP  40960               // double[CAPS] 16384
#define OFF_AACC  131072              // double[1024]  8192 (over cnt region)

struct Misc {
    double A_hist, A_exact, SpIn, p0, Pthr, Zd;
    float mlo, mhi, minv, klo, khi, kinv;
    float mlo_f, mhi_f, klo_f;
    unsigned cutPkey, minAkey;
    int AcntChain, nP, nC, lenP, lenM, cl;
};

// correctly-rounded fp32 x/T (Markstein; r = correctly-rounded fp32 1/T)
__device__ __forceinline__ float div_rn(float x, float T, float r) {
    float y = __fmul_rn(x, r);
    float e = __fmaf_rn(-T, y, x);
    return __fmaf_rn(e, r, y);
}
// order-preserving float<->uint maps (ascending)
__device__ __forceinline__ unsigned fmap(float x) {
    unsigned b = __float_as_uint(x);
    return (b & 0x80000000u) ? ~b : (b | 0x80000000u);
}
__device__ __forceinline__ float finv(unsigned k) {
    unsigned b = (k & 0x80000000u) ? (k & 0x7FFFFFFFu) : ~k;
    return __uint_as_float(b);
}
__device__ __forceinline__ int bin16(float s, float lo, float inv) {
    int j = (int)__fmul_rn(__fadd_rn(s, -lo), inv);
    return max(0, min(NBINS - 1, j));
}

__global__ void __launch_bounds__(TPB, 1) sampler_kernel(
    const float* __restrict__ logits, const float* __restrict__ temps,
    const int*   __restrict__ topks,  const float* __restrict__ topps,
    const float* __restrict__ minps,  const float* __restrict__ us,
    float* __restrict__ out, int out_size)
{
    extern __shared__ unsigned char sm[];
    double*   massH = (double*)(sm + OFF_MASS);
    unsigned* cntH  = (unsigned*)(sm + OFF_CNT);
    double*   redD  = (double*)(sm + OFF_REDD);
    int*      redI  = (int*)(sm + OFF_REDI);
    double*   binM  = (double*)(sm + OFF_BINM);
    int*      binC  = (int*)(sm + OFF_BINC);
    Misc*     msc   = (Misc*)(sm + OFF_MISC);
    float*    bufP  = (float*)(sm + OFF_BUFP);
    double*   bufPe = (double*)(sm + OFF_BUFPE);
    unsigned long long* bufS = (unsigned long long*)(sm + OFF_BUFS);
    double*   cumP  = (double*)(sm + OFF_CUMP);
    double*   Aacc  = (double*)(sm + OFF_AACC);

    const int row = blockIdx.x, tid = threadIdx.x;
    const float4* L4 = (const float4*)(logits + (size_t)row * V_COLS);
    const float T = temps[row];
    const float rT = (float)(1.0 / (double)T);
    const int   Kv = topks[row];
    const bool has_lp = (out_size >= B_ROWS + B_ROWS * V_COLS);
    const bool has_nt = (out_size >= B_ROWS + B_ROWS * V_COLS + B_ROWS);

    if (tid == 0) {
        msc->A_hist = 0.0; msc->A_exact = 0.0; msc->SpIn = 0.0; msc->p0 = 0.0; msc->Pthr = 0.0;
        msc->mlo = -40.0f; msc->mhi = 40.0f; msc->minv = 0.2f;
        msc->klo = -40.0f; msc->khi = 40.0f; msc->kinv = 0.2f;
        msc->cutPkey = 0xFFFFFFFFu; msc->minAkey = 0xFFFFFFFFu;
        msc->AcntChain = 0; msc->nP = 0; msc->nC = 0;
        msc->lenP = 0; msc->lenM = 0; msc->cl = 0;
    }
    __syncthreads();

    // ================= hierarchical per-lane histogram, 3 levels =================
    for (int level = 1; level <= 3; ++level) {
        for (int t = tid; t < NBINS * TPB; t += TPB) { massH[t] = 0.0; cntH[t] = 0u; }
        __syncthreads();
        const float mlo = msc->mlo, mhi = msc->mhi, minv = msc->minv;
        const float klo = msc->klo, khi = msc->khi, kinv = msc->kinv;

        for (int i = tid; i < NV4; i += TPB) {
            float4 x = L4[i];
            float xs[4] = {x.x, x.y, x.z, x.w};
            #pragma unroll
            for (int c = 0; c < 4; ++c) {
                float s = div_rn(xs[c], T, rT);
                if (s >= mlo && s < mhi) {
                    int b = bin16(s, mlo, minv);
                    massH[b * TPB + tid] += (double)__expf(s);
                }
                if (s >= klo && s < khi) {
                    int b = bin16(s, klo, kinv);
                    cntH[b * TPB + tid] += 1u;
                }
            }
        }
        __syncthreads();
        // reduce 16x1024 -> 16 (two stages)
        {
            int g = tid >> 6, sub = tid & 63;
            double pm = 0.0; int pc = 0;
            #pragma unroll
            for (int i = 0; i < 16; ++i) {
                pm += massH[g * TPB + sub + 64 * i];
                pc += (int)cntH[g * TPB + sub + 64 * i];
            }
            redD[g * 64 + sub] = pm; redI[g * 64 + sub] = pc;
        }
        __syncthreads();
        if (tid < NBINS) {
            double m = 0.0; int c = 0;
            for (int i = 0; i < 64; ++i) { m += redD[tid * 64 + i]; c += redI[tid * 64 + i]; }
            binM[tid] = m; binC[tid] = c;
        }
        __syncthreads();

        if (tid == 0) {
            if (level == 1) {
                double Z = 0.0;
                for (int b = 0; b < NBINS; ++b) Z += binM[b];
                msc->Zd = Z;
                msc->Pthr = (double)topps[row] * Z;
            }
            // --- mass chain straddle ---
            {
                const double A = msc->A_hist, P = msc->Pthr;
                double run = 0.0, above = 0.0, total = 0.0;
                int chosen = -1;
                for (int b = NBINS - 1; b >= 0; --b) {
                    double ri = run + binM[b];
                    if (chosen < 0 && A + run <= P && P < A + ri) { chosen = b; above = run; }
                    run = ri;
                }
                total = run;
                if (chosen < 0) {
                    if (A > P) { chosen = NBINS - 1; above = 0.0; }
                    else       { chosen = 0; above = total - binM[0]; }
                }
                msc->A_hist = A + above;
                float w = (msc->mhi - msc->mlo) * (1.0f / NBINS);
                float nlo = msc->mlo + chosen * w;
                float nhi = msc->mlo + (chosen + 1) * w;
                if (level < 3) { msc->mlo = nlo; msc->mhi = nhi; msc->minv = (float)NBINS / (nhi - nlo); }
                else           { msc->mlo_f = nlo; msc->mhi_f = nhi; }
            }
            // --- count chain straddle ---
            {
                const int Ac = msc->AcntChain;
                int run = 0, above = 0, total = 0, chosen = -1;
                for (int b = NBINS - 1; b >= 0; --b) {
                    int ri = run + binC[b];
                    if (chosen < 0 && Ac + run < Kv && Kv <= Ac + ri) { chosen = b; above = run; }
                    run = ri;
                }
                total = run;
                if (chosen < 0) {
                    if (Ac >= Kv) { chosen = NBINS - 1; above = 0; }
                    else          { chosen = 0; above = total - binC[0]; }
                }
                msc->AcntChain = Ac + above;
                float w = (msc->khi - msc->klo) * (1.0f / NBINS);
                float nlo = msc->klo + chosen * w;
                float nhi = msc->klo + (chosen + 1) * w;
                if (level < 3) { msc->klo = nlo; msc->khi = nhi; msc->kinv = (float)NBINS / (nhi - nlo); }
                else           { msc->klo_f = nlo; }
            }
        }
        __syncthreads();
    }

    // ================= collect pass (thresholds; self-consistent partition) =======
    Aacc[tid] = 0.0;
    float minAloc = FLT_MAX;
    const float mlo_f = msc->mlo_f, mhi_f = msc->mhi_f, klo_f = msc->klo_f;
    for (int i = tid; i < NV4; i += TPB) {
        float4 x = L4[i];
        float xs[4] = {x.x, x.y, x.z, x.w};
        #pragma unroll
        for (int c = 0; c < 4; ++c) {
            float s = div_rn(xs[c], T, rT);
            if (s >= mhi_f) {
                Aacc[tid] += (double)__expf(s);
                minAloc = fminf(minAloc, s);
            } else if (s >= mlo_f) {
                int q = atomicAdd(&msc->nP, 1);
                if (q < CAPP) bufP[q] = s;
            }
            if (s >= klo_f) {
                int q = atomicAdd(&msc->nC, 1);
                if (q < CAPS)
                    bufS[q] = (((unsigned long long)(~fmap(s))) << 32) | (unsigned)(4 * i + c);
            }
        }
    }
    // min-above reduce (warp shuffle + atomicMin on key)
    #pragma unroll
    for (int o = 16; o; o >>= 1) minAloc = fminf(minAloc, __shfl_xor_sync(~0u, minAloc, o));
    if ((tid & 31) == 0 && minAloc < FLT_MAX) atomicMin(&msc->minAkey, fmap(minAloc));
    __syncthreads();
    // A_exact reduce: 1024 doubles -> 1
    if (tid < 64) {
        double a = 0.0;
        #pragma unroll
        for (int i = 0; i < 16; ++i) a += Aacc[tid + 64 * i];
        redD[tid] = a;
    }
    __syncthreads();
    if (tid == 0) {
        double a = 0.0;
        for (int i = 0; i < 64; ++i) a += redD[i];
        msc->A_exact = a;
    }
    __syncthreads();

    // ================= top-p cut for logprobs: exact fp64 in-band =================
    const int nP = min(msc->nP, CAPP);
    const int nC = min(msc->nC, CAPS);
    for (int i = tid; i < nP; i += TPB) bufPe[i] = exp((double)bufP[i]);
    __syncthreads();
    {
        const double Aex = msc->A_exact, P = msc->Pthr;
        for (int i = tid; i < nP; i += TPB) {
            float ti = bufP[i];
            double g = 0.0;
            for (int w = 0; w < nP; ++w) if (bufP[w] > ti) g += bufPe[w];
            if (Aex + g <= P) {
                atomicMin(&msc->cutPkey, fmap(ti));
                atomicAdd(&msc->SpIn, bufPe[i]);
            }
        }
    }
    __syncthreads();
    float cutP;
    {
        unsigned ck = msc->cutPkey;
        if (ck != 0xFFFFFFFFu) cutP = finv(ck);
        else if (msc->minAkey != 0xFFFFFFFFu) cutP = finv(msc->minAkey);
        else cutP = -FLT_MAX;
    }
    const float lnS = (float)log(msc->A_exact + msc->SpIn);
    const double Pthr = msc->Pthr;

    // ================= bitonic sort: reference order (desc value, asc index) ======
    int n2 = 1; while (n2 < nC) n2 <<= 1;
    if (n2 < 2) n2 = 2;
    for (int i = tid; i < n2; i += TPB) if (i >= nC) bufS[i] = 0xFFFFFFFFFFFFFFFFULL;
    __syncthreads();
    for (int k = 2; k <= n2; k <<= 1) {
        for (int jj = k >> 1; jj > 0; jj >>= 1) {
            for (int i = tid; i < n2; i += TPB) {
                int ix = i ^ jj;
                if (ix > i) {
                    unsigned long long a = bufS[i], b = bufS[ix];
                    if (((i & k) == 0) == (a > b)) { bufS[i] = b; bufS[ix] = a; }
                }
            }
            __syncthreads();
        }
    }

    // ========== positional filtering (rank<K, excl-cumsum<=Pthr, p>=p0*minp) ======
    const int i0 = tid, i1 = tid + TPB;
    double pr0 = 0.0, pr1 = 0.0;
    if (i0 < nC) pr0 = exp((double)finv(~(unsigned)(bufS[i0] >> 32)));
    if (i1 < nC) pr1 = exp((double)finv(~(unsigned)(bufS[i1] >> 32)));
    if (i0 < n2) cumP[i0] = pr0;
    if (i1 < n2) cumP[i1] = pr1;
    if (i0 == 0) msc->p0 = pr0;
    __syncthreads();
    for (int off = 1; off < n2; off <<= 1) {
        double a0 = 0.0, a1 = 0.0;
        if (i0 < n2 && i0 >= off) a0 = cumP[i0 - off];
        if (i1 < n2 && i1 >= off) a1 = cumP[i1 - off];
        __syncthreads();
        if (i0 < n2) cumP[i0] += a0;
        if (i1 < n2) cumP[i1] += a1;
        __syncthreads();
    }
    {
        const double thrM = msc->p0 * (double)minps[row];
        int lp = 0, lm = 0;
        if (i0 < nC) { lp += (cumP[i0] - pr0 <= Pthr); lm += (pr0 >= thrM); }
        if (i1 < nC) { lp += (cumP[i1] - pr1 <= Pthr); lm += (pr1 >= thrM); }
        #pragma unroll
        for (int o = 16; o; o >>= 1) {
            lp += __shfl_xor_sync(~0u, lp, o);
            lm += __shfl_xor_sync(~0u, lm, o);
        }
        if ((tid & 31) == 0) { atomicAdd(&msc->lenP, lp); atomicAdd(&msc->lenM, lm); }
    }
    __syncthreads();
    const int nKeep = max(1, min(Kv, min(msc->lenP, msc->lenM)));
    const double target = (double)us[row] * cumP[nKeep - 1];
    {
        int cl = 0;
        if (i0 < nKeep) cl += (cumP[i0] < target);
        if (i1 < nKeep) cl += (cumP[i1] < target);
        #pragma unroll
        for (int o = 16; o; o >>= 1) cl += __shfl_xor_sync(~0u, cl, o);
        if ((tid & 31) == 0) atomicAdd(&msc->cl, cl);
    }
    __syncthreads();
    if (tid == 0) {
        int si = min(msc->cl, nKeep - 1);
        unsigned long long key = bufS[si];
        out[row] = (float)(int)(key & 0xFFFFFFFFu);
        if (has_nt) {
            float stok = finv(~(unsigned)(key >> 32));
            out[B_ROWS + (size_t)B_ROWS * V_COLS + row] = stok - lnS;
        }
    }

    // ================= Pass D: full-vocab logprobs =================
    if (has_lp) {
        float4* O4 = (float4*)(out + B_ROWS + (size_t)row * V_COLS);
        for (int i = tid; i < NV4; i += TPB) {
            float4 x = __ldcs(&L4[i]);
            float4 o;
            float s0 = div_rn(x.x, T, rT), s1 = div_rn(x.y, T, rT);
            float s2 = div_rn(x.z, T, rT), s3 = div_rn(x.w, T, rT);
            o.x = (s0 >= cutP) ? (s0 - lnS) : -FLT_MAX;
            o.y = (s1 >= cutP) ? (s1 - lnS) : -FLT_MAX;
            o.z = (s2 >= cutP) ? (s2 - lnS) : -FLT_MAX;
            o.w = (s3 >= cutP) ? (s3 - lnS) : -FLT_MAX;
            __stcs(&O4[i], o);
        }
    }
}

extern "C" void kernel_launch(void* const* d_in, const int* in_sizes, int n_in,
                              void* d_out, int out_size) {
    const float* logits = (const float*)d_in[0];
    const float* temps  = (const float*)d_in[1];
    const int*   topks  = (const int*)d_in[2];
    const float* topps  = (const float*)d_in[3];
    const float* minps  = (const float*)d_in[4];
    const float* us     = (const float*)d_in[5];
    float* out = (float*)d_out;

    cudaFuncSetAttribute(sampler_kernel, cudaFuncAttributeMaxDynamicSharedMemorySize, SMEM_TOTAL);
    sampler_kernel<<<B_ROWS, TPB, SMEM_TOTAL>>>(logits, temps, topks, topps, minps, us,
                                                out, out_size);
}